// round 4
// baseline (speedup 1.0000x reference)
#include <cuda_runtime.h>

// ---------------------------------------------------------------------------
// Earth4D multires hash encode, sm_103a
// Pipeline: init -> minmax reduce -> normalize (per point) -> encode (per point,enc,level)
// ---------------------------------------------------------------------------

#define TBL_SIZE  (1 << 19)
#define TBL_MASK  0x7FFFFu
#define MAXN      500000
#define DEG2RAD   0.017453292519943295f
#define EARTH_R   6371000.0f

// scratch (static device allocations are allowed)
__device__ float  g_red[8];        // mnx,mny,mnz, mxx,mxy,mxz, tmn,tmx
__device__ float4 g_u[MAXN];       // normalized (ux,uy,uz,ut) in [0,1]

// Resolutions. dims 0,1 always share a value (spatial: all equal; temporal: dims 0,1 equal).
// idx 0..15  : spatial levels  (base 16 -> 512, s = 2^(1/3))
// idx 16..31 : temporal levels (dims01: base 8 -> 32, s = 2^(2/15); dim2: base 8 -> 16, s = 2^(1/15))
__device__ int2 RES_TBL[32] = {
    {16,16},{20,20},{25,25},{32,32},{40,40},{51,51},{64,64},{81,81},
    {102,102},{128,128},{161,161},{203,203},{256,256},{323,323},{406,406},{512,512},
    {8,8},{9,8},{10,9},{11,9},{12,10},{13,10},{14,11},{15,11},
    {17,12},{18,12},{20,13},{22,13},{24,14},{27,15},{29,15},{32,16}
};

__device__ __forceinline__ void atomicMinF(float* a, float v) {
    if (v >= 0.0f) atomicMin((int*)a, __float_as_int(v));
    else           atomicMax((unsigned int*)a, __float_as_uint(v));
}
__device__ __forceinline__ void atomicMaxF(float* a, float v) {
    if (v >= 0.0f) atomicMax((int*)a, __float_as_int(v));
    else           atomicMin((unsigned int*)a, __float_as_uint(v));
}

__device__ __forceinline__ void ecef(float4 c, float& cx, float& cy, float& cz) {
    float latr = c.x * DEG2RAD;
    float lonr = c.y * DEG2RAD;
    float r    = EARTH_R + c.z;
    float sl, cl, so, co;
    sincosf(latr, &sl, &cl);
    sincosf(lonr, &so, &co);
    float rcl = r * cl;
    cx = rcl * co;
    cy = rcl * so;
    cz = r * sl;
}

__global__ void init_kernel() {
    int t = threadIdx.x;
    if (t < 8) {
        bool is_min = (t < 3) || (t == 6);
        g_red[t] = is_min ? __int_as_float(0x7F800000) : __int_as_float(0xFF800000);
    }
}

__global__ void __launch_bounds__(256) reduce_kernel(const float4* __restrict__ coords, int n) {
    float mn0 =  __int_as_float(0x7F800000), mn1 = mn0, mn2 = mn0, tmn = mn0;
    float mx0 = -mn0, mx1 = -mn0, mx2 = -mn0, tmx = -mn0;
    for (int i = blockIdx.x * blockDim.x + threadIdx.x; i < n; i += gridDim.x * blockDim.x) {
        float4 c = __ldg(&coords[i]);
        float cx, cy, cz;
        ecef(c, cx, cy, cz);
        mn0 = fminf(mn0, cx); mx0 = fmaxf(mx0, cx);
        mn1 = fminf(mn1, cy); mx1 = fmaxf(mx1, cy);
        mn2 = fminf(mn2, cz); mx2 = fmaxf(mx2, cz);
        tmn = fminf(tmn, c.w); tmx = fmaxf(tmx, c.w);
    }
    float v[8] = {mn0, mn1, mn2, mx0, mx1, mx2, tmn, tmx};
    #pragma unroll
    for (int o = 16; o > 0; o >>= 1) {
        #pragma unroll
        for (int q = 0; q < 8; q++) {
            float other = __shfl_xor_sync(0xFFFFFFFFu, v[q], o);
            bool is_min = (q < 3) || (q == 6);
            v[q] = is_min ? fminf(v[q], other) : fmaxf(v[q], other);
        }
    }
    __shared__ float s[8][8];
    int lane = threadIdx.x & 31, w = threadIdx.x >> 5;
    if (lane == 0) {
        #pragma unroll
        for (int q = 0; q < 8; q++) s[w][q] = v[q];
    }
    __syncthreads();
    if (threadIdx.x < 8) {
        int q = threadIdx.x;
        bool is_min = (q < 3) || (q == 6);
        float r = s[0][q];
        #pragma unroll
        for (int ww = 1; ww < 8; ww++)
            r = is_min ? fminf(r, s[ww][q]) : fmaxf(r, s[ww][q]);
        if (is_min) atomicMinF(&g_red[q], r);
        else        atomicMaxF(&g_red[q], r);
    }
}

__global__ void __launch_bounds__(256) normalize_kernel(const float4* __restrict__ coords, int n) {
    int i = blockIdx.x * blockDim.x + threadIdx.x;
    if (i >= n) return;
    float4 c = __ldg(&coords[i]);
    float cx, cy, cz;
    ecef(c, cx, cy, cz);
    float mnx = g_red[0], mny = g_red[1], mnz = g_red[2];
    float mxx = g_red[3], mxy = g_red[4], mxz = g_red[5];
    float tmn = g_red[6], tmx = g_red[7];
    float snx = (cx - mnx) / (mxx - mnx);
    float sny = (cy - mny) / (mxy - mny);
    float snz = (cz - mnz) / (mxz - mnz);
    float tn  = (c.w - tmn) / (tmx - tmn);
    float ts  = (tn * 2.0f - 1.0f) * 0.9f;
    float ux = fminf(fmaxf((snx + 1.0f) * 0.5f, 0.0f), 1.0f);
    float uy = fminf(fmaxf((sny + 1.0f) * 0.5f, 0.0f), 1.0f);
    float uz = fminf(fmaxf((snz + 1.0f) * 0.5f, 0.0f), 1.0f);
    float ut = fminf(fmaxf((ts  + 1.0f) * 0.5f, 0.0f), 1.0f);
    g_u[i] = make_float4(ux, uy, uz, ut);
}

// one thread per (point, encoding, level); 64 threads per point
__global__ void __launch_bounds__(256) encode_kernel(
    const float* __restrict__ t_xyz, const float* __restrict__ t_xyt,
    const float* __restrict__ t_yzt, const float* __restrict__ t_xzt,
    float2* __restrict__ out, int n)
{
    int gt  = blockIdx.x * 256 + threadIdx.x;
    int p   = gt >> 6;
    if (p >= n) return;
    int sub = gt & 63;
    int enc = sub >> 4;
    int lvl = sub & 15;

    float4 uv = g_u[p];   // broadcast across the 64 threads of this point

    // encoding -> (u0,u1,u2): enc0:(x,y,z) enc1:(x,y,t) enc2:(y,z,t) enc3:(x,z,t)
    float u0 = (enc == 2) ? uv.y : uv.x;
    float u1 = (enc <  2) ? uv.y : uv.z;
    float u2 = (enc == 0) ? uv.z : uv.w;

    const float* tp = (enc == 0) ? t_xyz : (enc == 1) ? t_xyt : (enc == 2) ? t_yzt : t_xzt;
    const float2* tab = (const float2*)tp + (size_t)lvl * TBL_SIZE;

    int2 rr = RES_TBL[((enc == 0) ? 0 : 16) + lvl];
    int r01 = rr.x, r2 = rr.y;

    float pos0 = u0 * ((float)r01 - 1.0f);
    float pos1 = u1 * ((float)r01 - 1.0f);
    float pos2 = u2 * ((float)r2  - 1.0f);
    int i0 = (int)pos0, i1 = (int)pos1, i2 = (int)pos2;   // pos >= 0 -> trunc == floor
    float w0 = pos0 - (float)i0;
    float w1 = pos1 - (float)i1;
    float w2 = pos2 - (float)i2;
    int j0 = min(i0 + 1, r01 - 1);
    int j1 = min(i1 + 1, r01 - 1);
    int j2 = min(i2 + 1, r2  - 1);

    unsigned hx0 = (unsigned)i0;
    unsigned hx1 = (unsigned)j0;
    unsigned hy0 = (unsigned)i1 * 2654435761u;
    unsigned hy1 = (unsigned)j1 * 2654435761u;
    unsigned hz0 = (unsigned)i2 * 805459861u;
    unsigned hz1 = (unsigned)j2 * 805459861u;

    float2 f0 = __ldg(&tab[(hx0 ^ hy0 ^ hz0) & TBL_MASK]);
    float2 f1 = __ldg(&tab[(hx1 ^ hy0 ^ hz0) & TBL_MASK]);
    float2 f2 = __ldg(&tab[(hx0 ^ hy1 ^ hz0) & TBL_MASK]);
    float2 f3 = __ldg(&tab[(hx1 ^ hy1 ^ hz0) & TBL_MASK]);
    float2 f4 = __ldg(&tab[(hx0 ^ hy0 ^ hz1) & TBL_MASK]);
    float2 f5 = __ldg(&tab[(hx1 ^ hy0 ^ hz1) & TBL_MASK]);
    float2 f6 = __ldg(&tab[(hx0 ^ hy1 ^ hz1) & TBL_MASK]);
    float2 f7 = __ldg(&tab[(hx1 ^ hy1 ^ hz1) & TBL_MASK]);

    float a0 = 1.0f - w0, b0 = 1.0f - w1, c0w = 1.0f - w2;
    float w00 = a0 * b0, w10 = w0 * b0, w01 = a0 * w1, w11 = w0 * w1;

    // corner weights in reference order c = 0..7 (bit d of c = offset along dim d)
    float accx, accy;
    accx = f0.x * (w00 * c0w);            accy = f0.y * (w00 * c0w);
    accx = fmaf(f1.x, w10 * c0w, accx);   accy = fmaf(f1.y, w10 * c0w, accy);
    accx = fmaf(f2.x, w01 * c0w, accx);   accy = fmaf(f2.y, w01 * c0w, accy);
    accx = fmaf(f3.x, w11 * c0w, accx);   accy = fmaf(f3.y, w11 * c0w, accy);
    accx = fmaf(f4.x, w00 * w2,  accx);   accy = fmaf(f4.y, w00 * w2,  accy);
    accx = fmaf(f5.x, w10 * w2,  accx);   accy = fmaf(f5.y, w10 * w2,  accy);
    accx = fmaf(f6.x, w01 * w2,  accx);   accy = fmaf(f6.y, w01 * w2,  accy);
    accx = fmaf(f7.x, w11 * w2,  accx);   accy = fmaf(f7.y, w11 * w2,  accy);

    out[(size_t)p * 64 + sub] = make_float2(accx, accy);
}

extern "C" void kernel_launch(void* const* d_in, const int* in_sizes, int n_in,
                              void* d_out, int out_size)
{
    const float* coords = (const float*)d_in[0];
    const float* t_xyz  = (const float*)d_in[1];
    const float* t_xyt  = (const float*)d_in[2];
    const float* t_yzt  = (const float*)d_in[3];
    const float* t_xzt  = (const float*)d_in[4];
    int n = in_sizes[0] / 4;

    init_kernel<<<1, 32>>>();
    reduce_kernel<<<232, 256>>>((const float4*)coords, n);
    normalize_kernel<<<(n + 255) / 256, 256>>>((const float4*)coords, n);
    long long total = (long long)n * 64;
    int blocks = (int)((total + 255) / 256);
    encode_kernel<<<blocks, 256>>>(t_xyz, t_xyt, t_yzt, t_xzt, (float2*)d_out, n);
}

// round 5
// speedup vs baseline: 2.9328x; 2.9328x over previous
#include <cuda_runtime.h>

// ---------------------------------------------------------------------------
// Earth4D multires hash encode, sm_103a
// init -> minmax reduce -> normalize -> densify small levels -> encode
// ---------------------------------------------------------------------------

#define TBL_SIZE  (1 << 19)
#define TBL_MASK  0x7FFFFu
#define MAXN      500000
#define DEG2RAD   0.017453292519943295f
#define EARTH_R   6371000.0f

#define SP_TOTAL   2111933        // dense cells, spatial levels 0..8
#define TM_TOTAL   77756          // dense cells per temporal encoding
#define DENSE_TOTAL (SP_TOTAL + 3 * TM_TOTAL)   // 2345201

__device__ float  g_red[8];                 // mnx,mny,mnz, mxx,mxy,mxz, tmn,tmx
__device__ float4 g_u[MAXN];                // normalized (ux,uy,uz,ut)
__device__ float4 g_dense[DENSE_TOTAL];     // densified levels, cell = (f[z], f[z+1])

// per-(enc*16+lvl) descriptor: {dense_offset(-1 = hashed), r01, r2, 0}
__constant__ int4 PAIR_DESC[64] = {
    // enc0: spatial (lvl 0..8 dense, 9..15 hashed)
    {0,16,16,0},{4096,20,20,0},{12096,25,25,0},{27721,32,32,0},
    {60489,40,40,0},{124489,51,51,0},{257140,64,64,0},{519284,81,81,0},
    {1050725,102,102,0},{-1,128,128,0},{-1,161,161,0},{-1,203,203,0},
    {-1,256,256,0},{-1,323,323,0},{-1,406,406,0},{-1,512,512,0},
    // enc1: xyt
    {2111933,8,8,0},{2112445,9,8,0},{2113093,10,9,0},{2113993,11,9,0},
    {2115082,12,10,0},{2116522,13,10,0},{2118212,14,11,0},{2120368,15,11,0},
    {2122843,17,12,0},{2126311,18,12,0},{2130199,20,13,0},{2135399,22,13,0},
    {2141691,24,14,0},{2149755,27,15,0},{2160690,29,15,0},{2173305,32,16,0},
    // enc2: yzt
    {2189689,8,8,0},{2190201,9,8,0},{2190849,10,9,0},{2191749,11,9,0},
    {2192838,12,10,0},{2194278,13,10,0},{2195968,14,11,0},{2198124,15,11,0},
    {2200599,17,12,0},{2204067,18,12,0},{2207955,20,13,0},{2213155,22,13,0},
    {2219447,24,14,0},{2227511,27,15,0},{2238446,29,15,0},{2251061,32,16,0},
    // enc3: xzt
    {2267445,8,8,0},{2267957,9,8,0},{2268605,10,9,0},{2269505,11,9,0},
    {2270594,12,10,0},{2272034,13,10,0},{2273724,14,11,0},{2275880,15,11,0},
    {2278355,17,12,0},{2281823,18,12,0},{2285711,20,13,0},{2290911,22,13,0},
    {2297203,24,14,0},{2305267,27,15,0},{2316202,29,15,0},{2328817,32,16,0}
};

// precompute-side tables
__constant__ int SP_OFF[10] = {0,4096,12096,27721,60489,124489,257140,519284,1050725,SP_TOTAL};
__constant__ int SPRES[9]   = {16,20,25,32,40,51,64,81,102};
__constant__ int TM_PRE[17] = {0,512,1160,2060,3149,4589,6279,8435,10910,14378,18266,23466,29758,37822,48757,61372,TM_TOTAL};
__constant__ int TR01[16]   = {8,9,10,11,12,13,14,15,17,18,20,22,24,27,29,32};
__constant__ int TR2[16]    = {8,8,9,9,10,10,11,11,12,12,13,13,14,15,15,16};

__device__ __forceinline__ void atomicMinF(float* a, float v) {
    if (v >= 0.0f) atomicMin((int*)a, __float_as_int(v));
    else           atomicMax((unsigned int*)a, __float_as_uint(v));
}
__device__ __forceinline__ void atomicMaxF(float* a, float v) {
    if (v >= 0.0f) atomicMax((int*)a, __float_as_int(v));
    else           atomicMin((unsigned int*)a, __float_as_uint(v));
}

__device__ __forceinline__ void ecef(float4 c, float& cx, float& cy, float& cz) {
    float latr = c.x * DEG2RAD;
    float lonr = c.y * DEG2RAD;
    float r    = EARTH_R + c.z;
    float sl, cl, so, co;
    sincosf(latr, &sl, &cl);
    sincosf(lonr, &so, &co);
    float rcl = r * cl;
    cx = rcl * co;
    cy = rcl * so;
    cz = r * sl;
}

__global__ void init_kernel() {
    int t = threadIdx.x;
    if (t < 8) {
        bool is_min = (t < 3) || (t == 6);
        g_red[t] = is_min ? __int_as_float(0x7F800000) : __int_as_float(0xFF800000);
    }
}

__global__ void __launch_bounds__(256) reduce_kernel(const float4* __restrict__ coords, int n) {
    float mn0 =  __int_as_float(0x7F800000), mn1 = mn0, mn2 = mn0, tmn = mn0;
    float mx0 = -mn0, mx1 = -mn0, mx2 = -mn0, tmx = -mn0;
    for (int i = blockIdx.x * blockDim.x + threadIdx.x; i < n; i += gridDim.x * blockDim.x) {
        float4 c = __ldg(&coords[i]);
        float cx, cy, cz;
        ecef(c, cx, cy, cz);
        mn0 = fminf(mn0, cx); mx0 = fmaxf(mx0, cx);
        mn1 = fminf(mn1, cy); mx1 = fmaxf(mx1, cy);
        mn2 = fminf(mn2, cz); mx2 = fmaxf(mx2, cz);
        tmn = fminf(tmn, c.w); tmx = fmaxf(tmx, c.w);
    }
    float v[8] = {mn0, mn1, mn2, mx0, mx1, mx2, tmn, tmx};
    #pragma unroll
    for (int o = 16; o > 0; o >>= 1) {
        #pragma unroll
        for (int q = 0; q < 8; q++) {
            float other = __shfl_xor_sync(0xFFFFFFFFu, v[q], o);
            bool is_min = (q < 3) || (q == 6);
            v[q] = is_min ? fminf(v[q], other) : fmaxf(v[q], other);
        }
    }
    __shared__ float s[8][8];
    int lane = threadIdx.x & 31, w = threadIdx.x >> 5;
    if (lane == 0) {
        #pragma unroll
        for (int q = 0; q < 8; q++) s[w][q] = v[q];
    }
    __syncthreads();
    if (threadIdx.x < 8) {
        int q = threadIdx.x;
        bool is_min = (q < 3) || (q == 6);
        float r = s[0][q];
        #pragma unroll
        for (int ww = 1; ww < 8; ww++)
            r = is_min ? fminf(r, s[ww][q]) : fmaxf(r, s[ww][q]);
        if (is_min) atomicMinF(&g_red[q], r);
        else        atomicMaxF(&g_red[q], r);
    }
}

__global__ void __launch_bounds__(256) normalize_kernel(const float4* __restrict__ coords, int n) {
    int i = blockIdx.x * blockDim.x + threadIdx.x;
    if (i >= n) return;
    float4 c = __ldg(&coords[i]);
    float cx, cy, cz;
    ecef(c, cx, cy, cz);
    float mnx = g_red[0], mny = g_red[1], mnz = g_red[2];
    float mxx = g_red[3], mxy = g_red[4], mxz = g_red[5];
    float tmn = g_red[6], tmx = g_red[7];
    float snx = (cx - mnx) / (mxx - mnx);
    float sny = (cy - mny) / (mxy - mny);
    float snz = (cz - mnz) / (mxz - mnz);
    float tn  = (c.w - tmn) / (tmx - tmn);
    float ts  = (tn * 2.0f - 1.0f) * 0.9f;
    float ux = fminf(fmaxf((snx + 1.0f) * 0.5f, 0.0f), 1.0f);
    float uy = fminf(fmaxf((sny + 1.0f) * 0.5f, 0.0f), 1.0f);
    float uz = fminf(fmaxf((snz + 1.0f) * 0.5f, 0.0f), 1.0f);
    float ut = fminf(fmaxf((ts  + 1.0f) * 0.5f, 0.0f), 1.0f);
    g_u[i] = make_float4(ux, uy, uz, ut);
}

// Materialize dense grids: cell (lx,ly,lz) = (tab[h(lx,ly,lz)], tab[h(lx,ly,min(lz+1,r2-1))])
__global__ void __launch_bounds__(256) densify_kernel(
    const float* __restrict__ t_xyz, const float* __restrict__ t_xyt,
    const float* __restrict__ t_yzt, const float* __restrict__ t_xzt)
{
    int cell = blockIdx.x * 256 + threadIdx.x;
    if (cell >= DENSE_TOTAL) return;

    const float2* tab;
    int lvl, r01, r2, local;
    if (cell < SP_TOTAL) {
        lvl = 8;
        #pragma unroll
        for (int l = 8; l >= 1; l--) { if (cell < SP_OFF[l]) lvl = l - 1; }
        local = cell - SP_OFF[lvl];
        r01 = SPRES[lvl]; r2 = r01;
        tab = (const float2*)t_xyz;
    } else {
        int rem = cell - SP_TOTAL;
        int e = rem / TM_TOTAL;
        int lr = rem - e * TM_TOTAL;
        lvl = 15;
        #pragma unroll
        for (int l = 15; l >= 1; l--) { if (lr < TM_PRE[l]) lvl = l - 1; }
        local = lr - TM_PRE[lvl];
        r01 = TR01[lvl]; r2 = TR2[lvl];
        tab = (const float2*)((e == 0) ? t_xyt : (e == 1) ? t_yzt : t_xzt);
    }
    tab += (size_t)lvl * TBL_SIZE;

    int lz  = local % r2;
    int tmp = local / r2;
    int ly  = tmp % r01;
    int lx  = tmp / r01;
    int lz2 = min(lz + 1, r2 - 1);

    unsigned hxy = (unsigned)lx ^ ((unsigned)ly * 2654435761u);
    unsigned i1 = (hxy ^ ((unsigned)lz  * 805459861u)) & TBL_MASK;
    unsigned i2 = (hxy ^ ((unsigned)lz2 * 805459861u)) & TBL_MASK;
    float2 a = __ldg(&tab[i1]);
    float2 b = __ldg(&tab[i2]);
    g_dense[cell] = make_float4(a.x, a.y, b.x, b.y);
}

// block = 32 points x 8 (enc,lvl) pairs; warp = one pair across 32 points
__global__ void __launch_bounds__(256) encode_kernel(
    const float* __restrict__ t_xyz, float2* __restrict__ out, int n)
{
    int lane = threadIdx.x & 31;
    int w    = threadIdx.x >> 5;
    int p    = blockIdx.x * 32 + lane;
    int pair = blockIdx.y * 8 + w;
    int enc  = pair >> 4;
    int lvl  = pair & 15;

    __shared__ float2 stage[32][9];
    float accx = 0.0f, accy = 0.0f;

    if (p < n) {
        float4 uv = g_u[p];
        float u0 = (enc == 2) ? uv.y : uv.x;
        float u1 = (enc <  2) ? uv.y : uv.z;
        float u2 = (enc == 0) ? uv.z : uv.w;

        int4 d = PAIR_DESC[pair];
        int r01 = d.y, r2 = d.z;

        float pos0 = u0 * ((float)r01 - 1.0f);
        float pos1 = u1 * ((float)r01 - 1.0f);
        float pos2 = u2 * ((float)r2  - 1.0f);
        int i0 = (int)pos0, i1 = (int)pos1, i2 = (int)pos2;
        float w0 = pos0 - (float)i0;
        float w1 = pos1 - (float)i1;
        float w2 = pos2 - (float)i2;
        int j0 = min(i0 + 1, r01 - 1);
        int j1 = min(i1 + 1, r01 - 1);

        float2 f0, f1, f2, f3, f4, f5, f6, f7;
        if (d.x >= 0) {
            // dense path: 4 float4 loads give all 8 corners (z-pairs packed)
            const float4* g = g_dense + d.x;
            float4 q00 = __ldg(&g[(i0 * r01 + i1) * r2 + i2]);
            float4 q10 = __ldg(&g[(j0 * r01 + i1) * r2 + i2]);
            float4 q01 = __ldg(&g[(i0 * r01 + j1) * r2 + i2]);
            float4 q11 = __ldg(&g[(j0 * r01 + j1) * r2 + i2]);
            f0 = make_float2(q00.x, q00.y); f4 = make_float2(q00.z, q00.w);
            f1 = make_float2(q10.x, q10.y); f5 = make_float2(q10.z, q10.w);
            f2 = make_float2(q01.x, q01.y); f6 = make_float2(q01.z, q01.w);
            f3 = make_float2(q11.x, q11.y); f7 = make_float2(q11.z, q11.w);
        } else {
            // hashed path (spatial levels 9..15)
            const float2* tab = (const float2*)t_xyz + (size_t)lvl * TBL_SIZE;
            int j2 = min(i2 + 1, r2 - 1);
            unsigned hx0 = (unsigned)i0;
            unsigned hx1 = (unsigned)j0;
            unsigned hy0 = (unsigned)i1 * 2654435761u;
            unsigned hy1 = (unsigned)j1 * 2654435761u;
            unsigned hz0 = (unsigned)i2 * 805459861u;
            unsigned hz1 = (unsigned)j2 * 805459861u;
            f0 = __ldg(&tab[(hx0 ^ hy0 ^ hz0) & TBL_MASK]);
            f1 = __ldg(&tab[(hx1 ^ hy0 ^ hz0) & TBL_MASK]);
            f2 = __ldg(&tab[(hx0 ^ hy1 ^ hz0) & TBL_MASK]);
            f3 = __ldg(&tab[(hx1 ^ hy1 ^ hz0) & TBL_MASK]);
            f4 = __ldg(&tab[(hx0 ^ hy0 ^ hz1) & TBL_MASK]);
            f5 = __ldg(&tab[(hx1 ^ hy0 ^ hz1) & TBL_MASK]);
            f6 = __ldg(&tab[(hx0 ^ hy1 ^ hz1) & TBL_MASK]);
            f7 = __ldg(&tab[(hx1 ^ hy1 ^ hz1) & TBL_MASK]);
        }

        float a0 = 1.0f - w0, b0 = 1.0f - w1, c0w = 1.0f - w2;
        float w00 = a0 * b0, w10 = w0 * b0, w01 = a0 * w1, w11 = w0 * w1;

        accx = f0.x * (w00 * c0w);            accy = f0.y * (w00 * c0w);
        accx = fmaf(f1.x, w10 * c0w, accx);   accy = fmaf(f1.y, w10 * c0w, accy);
        accx = fmaf(f2.x, w01 * c0w, accx);   accy = fmaf(f2.y, w01 * c0w, accy);
        accx = fmaf(f3.x, w11 * c0w, accx);   accy = fmaf(f3.y, w11 * c0w, accy);
        accx = fmaf(f4.x, w00 * w2,  accx);   accy = fmaf(f4.y, w00 * w2,  accy);
        accx = fmaf(f5.x, w10 * w2,  accx);   accy = fmaf(f5.y, w10 * w2,  accy);
        accx = fmaf(f6.x, w01 * w2,  accx);   accy = fmaf(f6.y, w01 * w2,  accy);
        accx = fmaf(f7.x, w11 * w2,  accx);   accy = fmaf(f7.y, w11 * w2,  accy);
    }

    stage[lane][w] = make_float2(accx, accy);
    __syncthreads();

    // coalesced writeback: 8 consecutive pairs per point = 64B contiguous
    int pl = threadIdx.x >> 3, q = threadIdx.x & 7;
    int pp = blockIdx.x * 32 + pl;
    if (pp < n)
        out[(size_t)pp * 64 + blockIdx.y * 8 + q] = stage[pl][q];
}

extern "C" void kernel_launch(void* const* d_in, const int* in_sizes, int n_in,
                              void* d_out, int out_size)
{
    const float* coords = (const float*)d_in[0];
    const float* t_xyz  = (const float*)d_in[1];
    const float* t_xyt  = (const float*)d_in[2];
    const float* t_yzt  = (const float*)d_in[3];
    const float* t_xzt  = (const float*)d_in[4];
    int n = in_sizes[0] / 4;

    init_kernel<<<1, 32>>>();
    reduce_kernel<<<232, 256>>>((const float4*)coords, n);
    normalize_kernel<<<(n + 255) / 256, 256>>>((const float4*)coords, n);
    densify_kernel<<<(DENSE_TOTAL + 255) / 256, 256>>>(t_xyz, t_xyt, t_yzt, t_xzt);
    dim3 grid((n + 31) / 32, 8);
    encode_kernel<<<grid, 256>>>(t_xyz, (float2*)d_out, n);
}